// round 6
// baseline (speedup 1.0000x reference)
#include <cuda_runtime.h>
#include <cuda_bf16.h>
#include <cstdint>

#define NN   100000
#define D    128
#define MAXE 3400000
#define NT   ((NN + 127) / 128)
#define TILE_U4 2048   // uint4 per 32KB bf16 128x128 image

// ---------------------------------------------------------------------------
// Allocation-free scratch
// ---------------------------------------------------------------------------
__device__ float g_h0[(size_t)NN * D];
__device__ float g_h1[(size_t)NN * D];
__device__ int   g_cnt[NN];
__device__ int   g_inc[NN];
__device__ int   g_rs[NN];
__device__ int   g_cur[NN];
__device__ int   g_srcs[MAXE];
__device__ int   g_bsums[128];
__device__ uint4 g_w_hi[3 * TILE_U4];
__device__ uint4 g_w_lo[3 * TILE_U4];

static __device__ __forceinline__ float4 add4(float4 a, float4 b) {
    return make_float4(a.x + b.x, a.y + b.y, a.z + b.z, a.w + b.w);
}

static __device__ __forceinline__ uint32_t s2u(const void* p) {
    uint32_t a;
    asm("{ .reg .u64 t; cvta.to.shared.u64 t, %1; cvt.u32.u64 %0, t; }"
        : "=r"(a) : "l"(p));
    return a;
}

static __device__ __forceinline__ uint32_t pack_bf2(float a, float b) {
    __nv_bfloat162 t = __floats2bfloat162_rn(a, b);
    return *(uint32_t*)&t;
}

static __device__ __forceinline__ void mma16816(float* c, const uint32_t* a,
                                                uint32_t b0, uint32_t b1) {
    asm volatile(
        "mma.sync.aligned.m16n8k16.row.col.f32.bf16.bf16.f32 "
        "{%0,%1,%2,%3}, {%4,%5,%6,%7}, {%8,%9}, {%0,%1,%2,%3};"
        : "+f"(c[0]), "+f"(c[1]), "+f"(c[2]), "+f"(c[3])
        : "r"(a[0]), "r"(a[1]), "r"(a[2]), "r"(a[3]), "r"(b0), "r"(b1));
}

static __device__ __forceinline__ void ldsm_x4(uint32_t* r, uint32_t addr) {
    asm volatile("ldmatrix.sync.aligned.m8n8.x4.shared.b16 {%0,%1,%2,%3}, [%4];"
                 : "=r"(r[0]), "=r"(r[1]), "=r"(r[2]), "=r"(r[3]) : "r"(addr));
}
static __device__ __forceinline__ void ldsm_x4t(uint32_t* r, uint32_t addr) {
    asm volatile("ldmatrix.sync.aligned.m8n8.x4.trans.shared.b16 {%0,%1,%2,%3}, [%4];"
                 : "=r"(r[0]), "=r"(r[1]), "=r"(r[2]), "=r"(r[3]) : "r"(addr));
}

// tile byte offset: row-major 128x128 bf16, 256B/row, XOR-swizzled 16B groups
static __device__ __forceinline__ uint32_t toff(int row, int g) {
    return (uint32_t)row * 256u + (uint32_t)((g ^ (row & 7)) << 4);
}

// ---------------------------------------------------------------------------
// CSR build
// ---------------------------------------------------------------------------
__global__ void zero_cnt_kernel() {
    int i = blockIdx.x * blockDim.x + threadIdx.x;
    if (i < NN) g_cnt[i] = 0;
}

__global__ void hist_kernel(const int* __restrict__ ei, int nE) {
    int e = blockIdx.x * blockDim.x + threadIdx.x;
    if (e < nE) atomicAdd(&g_cnt[ei[nE + e]], 1);
}

__global__ void scan1_kernel() {
    __shared__ int sm[1024];
    int t = threadIdx.x, b = blockIdx.x;
    int i = b * 1024 + t;
    sm[t] = (i < NN) ? g_cnt[i] : 0;
    __syncthreads();
    #pragma unroll
    for (int off = 1; off < 1024; off <<= 1) {
        int add = (t >= off) ? sm[t - off] : 0;
        __syncthreads();
        sm[t] += add;
        __syncthreads();
    }
    if (i < NN) g_inc[i] = sm[t];
    if (t == 1023) g_bsums[b] = sm[t];
}

__global__ void scan2_kernel(int nb) {
    __shared__ int sm[128];
    int t = threadIdx.x;
    int v = (t < nb) ? g_bsums[t] : 0;
    sm[t] = v;
    __syncthreads();
    #pragma unroll
    for (int off = 1; off < 128; off <<= 1) {
        int add = (t >= off) ? sm[t - off] : 0;
        __syncthreads();
        sm[t] += add;
        __syncthreads();
    }
    if (t < nb) g_bsums[t] = sm[t] - v;
}

__global__ void scan3_kernel() {
    int i = blockIdx.x * blockDim.x + threadIdx.x;
    if (i < NN) {
        int rs = g_inc[i] - g_cnt[i] + g_bsums[i >> 10];
        g_rs[i] = rs;
        g_cur[i] = rs;
    }
}

__global__ void fill_kernel(const int* __restrict__ ei, int nE) {
    int e = blockIdx.x * blockDim.x + threadIdx.x;
    if (e < nE) {
        int s = ei[e], d = ei[nE + e];
        int pos = atomicAdd(&g_cur[d], 1);
        g_srcs[pos] = s;
    }
}

// ---------------------------------------------------------------------------
// Prep W: fp32 [k][n] -> bf16 hi/lo swizzled images. grid=3.
// ---------------------------------------------------------------------------
__global__ void prep_w_kernel(const float* __restrict__ W1,
                              const float* __restrict__ W2,
                              const float* __restrict__ W3) {
    const float* W = (blockIdx.x == 0) ? W1 : (blockIdx.x == 1) ? W2 : W3;
    char* hi = (char*)g_w_hi + (size_t)blockIdx.x * 32768;
    char* lo = (char*)g_w_lo + (size_t)blockIdx.x * 32768;
    for (int i = threadIdx.x; i < D * D / 4; i += blockDim.x) {
        int k = i >> 5, c4 = i & 31;
        float4 v = ((const float4*)W)[i];
        float hx = __bfloat162float(__float2bfloat16(v.x));
        float hy = __bfloat162float(__float2bfloat16(v.y));
        float hz = __bfloat162float(__float2bfloat16(v.z));
        float hw = __bfloat162float(__float2bfloat16(v.w));
        uint2 hv = make_uint2(pack_bf2(v.x, v.y), pack_bf2(v.z, v.w));
        uint2 lv = make_uint2(pack_bf2(v.x - hx, v.y - hy), pack_bf2(v.z - hz, v.w - hw));
        uint32_t off = toff(k, c4 >> 1) + (c4 & 1) * 8;
        *(uint2*)(hi + off) = hv;
        *(uint2*)(lo + off) = lv;
    }
}

// ---------------------------------------------------------------------------
// Shared smem layout for both layer kernels
// ---------------------------------------------------------------------------
#define WH_OFF 0
#define WL_OFF 32768
#define AH_OFF 65536
#define AL_OFF 98304
#define BIAS_OFF 131072
#define SM_TOTAL (131072 + 512)

// MMA mainloop + epilogue, shared by both layer kernels.
static __device__ __forceinline__ void mma_tile_and_store(
    uint32_t sb, int wid, int lane, int row0,
    const char* smem, float* __restrict__ hout) {

    int mrow = wid * 16;
    float acc[16][4];
    #pragma unroll
    for (int i = 0; i < 16; i++)
        #pragma unroll
        for (int j = 0; j < 4; j++) acc[i][j] = 0.f;

    int arow = mrow + (lane & 15);
    int asel = lane >> 4;
    int axor = arow & 7;
    uint32_t a_base = sb + AH_OFF + (uint32_t)arow * 256u;
    int brow = lane & 15;
    int bsel = lane >> 4;

    #pragma unroll
    for (int ks = 0; ks < 8; ks++) {
        uint32_t ag = (uint32_t)(((ks * 2 + asel) ^ axor) << 4);
        uint32_t ahi[4], alo[4];
        ldsm_x4(ahi, a_base + ag);
        ldsm_x4(alo, a_base + 32768u + ag);

        int brr = ks * 16 + brow;
        uint32_t b_base = sb + WH_OFF + (uint32_t)brr * 256u;
        int bxor = brr & 7;

        #pragma unroll
        for (int p = 0; p < 8; p++) {
            uint32_t bg = (uint32_t)(((p * 2 + bsel) ^ bxor) << 4);
            uint32_t bh[4], bl[4];
            ldsm_x4t(bh, b_base + bg);
            ldsm_x4t(bl, b_base + 32768u + bg);
            mma16816(acc[2 * p],     ahi, bh[0], bh[1]);
            mma16816(acc[2 * p + 1], ahi, bh[2], bh[3]);
            mma16816(acc[2 * p],     ahi, bl[0], bl[1]);
            mma16816(acc[2 * p + 1], ahi, bl[2], bl[3]);
            mma16816(acc[2 * p],     alo, bh[0], bh[1]);
            mma16816(acc[2 * p + 1], alo, bh[2], bh[3]);
        }
    }

    const float* bs = (const float*)(smem + BIAS_OFF);
    int rbase = mrow + (lane >> 2);
    int col0 = (lane & 3) * 2;
    #pragma unroll
    for (int half = 0; half < 2; half++) {
        int grow = row0 + rbase + half * 8;
        if (grow < NN) {
            float* op = hout + (size_t)grow * D;
            #pragma unroll
            for (int nt = 0; nt < 16; nt++) {
                int c = nt * 8 + col0;
                float2 o;
                o.x = fmaxf(acc[nt][half * 2 + 0] + bs[c], 0.f);
                o.y = fmaxf(acc[nt][half * 2 + 1] + bs[c + 1], 0.f);
                *(float2*)(op + c) = o;
            }
        }
    }
}

static __device__ __forceinline__ void stage_w_bias(
    char* smem, const uint4* __restrict__ Whi, const uint4* __restrict__ Wlo,
    const float* __restrict__ bias, int tid) {
    #pragma unroll
    for (int t = 0; t < 8; t++) {
        int i = tid + t * 256;
        ((uint4*)(smem + WH_OFF))[i] = Whi[i];
        ((uint4*)(smem + WL_OFF))[i] = Wlo[i];
    }
    if (tid < 32) ((float4*)(smem + BIAS_OFF))[tid] = ((const float4*)bias)[tid];
}

// ---------------------------------------------------------------------------
// Layer 1 (persistent, fused gather+GEMM): for each 128-row tile,
// gather h = x + sum_neighbors(x) straight into bf16 hi/lo smem, then MMA.
// ---------------------------------------------------------------------------
__global__ __launch_bounds__(256, 1)
void layer1_fused_kernel(const float* __restrict__ x,
                         const uint4* __restrict__ Whi, const uint4* __restrict__ Wlo,
                         const float* __restrict__ bias,
                         float* __restrict__ hout) {
    extern __shared__ char smem[];
    uint32_t sb = s2u(smem);
    int tid = threadIdx.x, wid = tid >> 5, lane = tid & 31;

    stage_w_bias(smem, Whi, Wlo, bias, tid);
    const float4* xv = (const float4*)x;

    for (int tile = blockIdx.x; tile < NT; tile += gridDim.x) {
        __syncthreads();   // W ready (1st iter) / prior MMA done reading A bufs
        // gather-stage: warp handles 16 rows; lane owns cols [lane*4, lane*4+4)
        for (int r = 0; r < 16; r++) {
            int row = wid * 16 + r;
            int n = tile * 128 + row;
            float4 s = make_float4(0.f, 0.f, 0.f, 0.f);
            if (n < NN) {
                float4 a0 = xv[(size_t)n * 32 + lane];
                float4 a1 = make_float4(0.f, 0.f, 0.f, 0.f);
                float4 a2 = a1, a3 = a1;
                int c = g_cnt[n];
                const int* sp = g_srcs + g_rs[n];
                int j = 0;
                for (; j + 4 <= c; j += 4) {
                    int s0 = sp[j], s1 = sp[j + 1], s2 = sp[j + 2], s3 = sp[j + 3];
                    a0 = add4(a0, xv[(size_t)s0 * 32 + lane]);
                    a1 = add4(a1, xv[(size_t)s1 * 32 + lane]);
                    a2 = add4(a2, xv[(size_t)s2 * 32 + lane]);
                    a3 = add4(a3, xv[(size_t)s3 * 32 + lane]);
                }
                for (; j < c; j++)
                    a0 = add4(a0, xv[(size_t)sp[j] * 32 + lane]);
                s = add4(add4(a0, a1), add4(a2, a3));
            }
            float hx = __bfloat162float(__float2bfloat16(s.x));
            float hy = __bfloat162float(__float2bfloat16(s.y));
            float hz = __bfloat162float(__float2bfloat16(s.z));
            float hw = __bfloat162float(__float2bfloat16(s.w));
            uint2 hv = make_uint2(pack_bf2(s.x, s.y), pack_bf2(s.z, s.w));
            uint2 lv = make_uint2(pack_bf2(s.x - hx, s.y - hy), pack_bf2(s.z - hz, s.w - hw));
            uint32_t off = toff(row, lane >> 1) + (lane & 1) * 8;
            *(uint2*)(smem + AH_OFF + off) = hv;
            *(uint2*)(smem + AL_OFF + off) = lv;
        }
        __syncthreads();
        mma_tile_and_store(sb, wid, lane, tile * 128, smem, hout);
    }
}

// ---------------------------------------------------------------------------
// Layers 2/3 (persistent): W staged once; A tile prefetched into registers
// for the NEXT tile while the current tile's MMA runs.
// ---------------------------------------------------------------------------
__global__ __launch_bounds__(256, 1)
void layer_kernel(const float* __restrict__ hin,
                  const uint4* __restrict__ Whi, const uint4* __restrict__ Wlo,
                  const float* __restrict__ bias,
                  float* __restrict__ hout) {
    extern __shared__ char smem[];
    uint32_t sb = s2u(smem);
    int tid = threadIdx.x, wid = tid >> 5, lane = tid & 31;

    stage_w_bias(smem, Whi, Wlo, bias, tid);

    float4 pre[16];
    int tile = blockIdx.x;
    // prefetch first tile
    #pragma unroll
    for (int t = 0; t < 16; t++) {
        int i = tid + t * 256;
        int row = i >> 5, c4 = i & 31;
        int grow = tile * 128 + row;
        pre[t] = (tile < NT && grow < NN)
               ? ((const float4*)(hin + (size_t)grow * D))[c4]
               : make_float4(0.f, 0.f, 0.f, 0.f);
    }

    for (; tile < NT; tile += gridDim.x) {
        __syncthreads();   // prior MMA done reading A bufs / W ready
        // convert registers -> smem hi/lo
        #pragma unroll
        for (int t = 0; t < 16; t++) {
            int i = tid + t * 256;
            int row = i >> 5, c4 = i & 31;
            float4 v = pre[t];
            float hx = __bfloat162float(__float2bfloat16(v.x));
            float hy = __bfloat162float(__float2bfloat16(v.y));
            float hz = __bfloat162float(__float2bfloat16(v.z));
            float hw = __bfloat162float(__float2bfloat16(v.w));
            uint2 hv = make_uint2(pack_bf2(v.x, v.y), pack_bf2(v.z, v.w));
            uint2 lv = make_uint2(pack_bf2(v.x - hx, v.y - hy), pack_bf2(v.z - hz, v.w - hw));
            uint32_t off = toff(row, c4 >> 1) + (c4 & 1) * 8;
            *(uint2*)(smem + AH_OFF + off) = hv;
            *(uint2*)(smem + AL_OFF + off) = lv;
        }
        __syncthreads();
        // issue next tile's loads (land during MMA)
        int next = tile + gridDim.x;
        if (next < NT) {
            #pragma unroll
            for (int t = 0; t < 16; t++) {
                int i = tid + t * 256;
                int row = i >> 5, c4 = i & 31;
                int grow = next * 128 + row;
                pre[t] = (grow < NN)
                       ? ((const float4*)(hin + (size_t)grow * D))[c4]
                       : make_float4(0.f, 0.f, 0.f, 0.f);
            }
        }
        mma_tile_and_store(sb, wid, lane, tile * 128, smem, hout);
    }
}

// ---------------------------------------------------------------------------
extern "C" void kernel_launch(void* const* d_in, const int* in_sizes, int n_in,
                              void* d_out, int out_size) {
    const float* x  = (const float*)d_in[0];
    const float* W1 = (const float*)d_in[1];
    const float* b1 = (const float*)d_in[2];
    const float* W2 = (const float*)d_in[3];
    const float* b2 = (const float*)d_in[4];
    const float* W3 = (const float*)d_in[5];
    const float* b3 = (const float*)d_in[6];
    const int*   ei = (const int*)d_in[7];   // int32 (JAX x64 disabled)
    float* out = (float*)d_out;

    int nE = in_sizes[7] / 2;
    if (nE > MAXE) nE = MAXE;

    float *h0, *h1;
    uint4 *wHi, *wLo;
    cudaGetSymbolAddress((void**)&h0, g_h0);
    cudaGetSymbolAddress((void**)&h1, g_h1);
    cudaGetSymbolAddress((void**)&wHi, g_w_hi);
    cudaGetSymbolAddress((void**)&wLo, g_w_lo);

    int nsm = 148;
    {
        cudaDeviceProp prop;
        if (cudaGetDeviceProperties(&prop, 0) == cudaSuccess)
            nsm = prop.multiProcessorCount;
    }

    // --- CSR build + weight prep ---
    zero_cnt_kernel<<<(NN + 255) / 256, 256>>>();
    prep_w_kernel<<<3, 256>>>(W1, W2, W3);
    hist_kernel<<<(nE + 255) / 256, 256>>>(ei, nE);
    int nb = (NN + 1023) / 1024;
    scan1_kernel<<<nb, 1024>>>();
    scan2_kernel<<<1, 128>>>(nb);
    scan3_kernel<<<(NN + 255) / 256, 256>>>();
    fill_kernel<<<(nE + 255) / 256, 256>>>(ei, nE);

    // --- layer 1: fused gather + GEMM ---
    cudaFuncSetAttribute(layer1_fused_kernel,
                         cudaFuncAttributeMaxDynamicSharedMemorySize, SM_TOTAL);
    cudaFuncSetAttribute(layer_kernel,
                         cudaFuncAttributeMaxDynamicSharedMemorySize, SM_TOTAL);
    layer1_fused_kernel<<<nsm, 256, SM_TOTAL>>>(x, wHi, wLo, b1, h1);

    // --- layers 2/3 ---
    layer_kernel<<<nsm, 256, SM_TOTAL>>>(h1, wHi + TILE_U4,     wLo + TILE_U4,     b2, h0);
    layer_kernel<<<nsm, 256, SM_TOTAL>>>(h0, wHi + 2 * TILE_U4, wLo + 2 * TILE_U4, b3, out);
}

// round 7
// speedup vs baseline: 1.3750x; 1.3750x over previous
#include <cuda_runtime.h>
#include <cuda_bf16.h>
#include <cstdint>

#define NN   100000
#define D    128
#define MAXE 3400000
#define NT   ((NN + 127) / 128)
#define TILE_U4 2048   // uint4 per 32KB bf16 128x128 image

// ---------------------------------------------------------------------------
// Allocation-free scratch
// ---------------------------------------------------------------------------
__device__ float g_h0[(size_t)NN * D];
__device__ float g_h1[(size_t)NN * D];
__device__ int   g_cnt[NN];
__device__ int   g_inc[NN];
__device__ int   g_rs[NN];
__device__ int   g_cur[NN];
__device__ int   g_srcs[MAXE];
__device__ int   g_bsums[128];
__device__ uint4 g_w_hi[3 * TILE_U4];
__device__ uint4 g_w_lo[3 * TILE_U4];

static __device__ __forceinline__ float4 add4(float4 a, float4 b) {
    return make_float4(a.x + b.x, a.y + b.y, a.z + b.z, a.w + b.w);
}

static __device__ __forceinline__ uint32_t s2u(const void* p) {
    uint32_t a;
    asm("{ .reg .u64 t; cvta.to.shared.u64 t, %1; cvt.u32.u64 %0, t; }"
        : "=r"(a) : "l"(p));
    return a;
}

static __device__ __forceinline__ uint32_t pack_bf2(float a, float b) {
    __nv_bfloat162 t = __floats2bfloat162_rn(a, b);
    return *(uint32_t*)&t;
}

static __device__ __forceinline__ void mma16816(float* c, const uint32_t* a,
                                                uint32_t b0, uint32_t b1) {
    asm volatile(
        "mma.sync.aligned.m16n8k16.row.col.f32.bf16.bf16.f32 "
        "{%0,%1,%2,%3}, {%4,%5,%6,%7}, {%8,%9}, {%0,%1,%2,%3};"
        : "+f"(c[0]), "+f"(c[1]), "+f"(c[2]), "+f"(c[3])
        : "r"(a[0]), "r"(a[1]), "r"(a[2]), "r"(a[3]), "r"(b0), "r"(b1));
}

static __device__ __forceinline__ void ldsm_x4(uint32_t* r, uint32_t addr) {
    asm volatile("ldmatrix.sync.aligned.m8n8.x4.shared.b16 {%0,%1,%2,%3}, [%4];"
                 : "=r"(r[0]), "=r"(r[1]), "=r"(r[2]), "=r"(r[3]) : "r"(addr));
}
static __device__ __forceinline__ void ldsm_x4t(uint32_t* r, uint32_t addr) {
    asm volatile("ldmatrix.sync.aligned.m8n8.x4.trans.shared.b16 {%0,%1,%2,%3}, [%4];"
                 : "=r"(r[0]), "=r"(r[1]), "=r"(r[2]), "=r"(r[3]) : "r"(addr));
}

// tile byte offset: row-major 128x128 bf16, 256B/row, XOR-swizzled 16B groups
static __device__ __forceinline__ uint32_t toff(int row, int g) {
    return (uint32_t)row * 256u + (uint32_t)((g ^ (row & 7)) << 4);
}

// ---------------------------------------------------------------------------
// CSR build
// ---------------------------------------------------------------------------
__global__ void zero_cnt_kernel() {
    int i = blockIdx.x * blockDim.x + threadIdx.x;
    if (i < NN) g_cnt[i] = 0;
}

__global__ void hist_kernel(const int* __restrict__ ei, int nE) {
    int e = blockIdx.x * blockDim.x + threadIdx.x;
    if (e < nE) atomicAdd(&g_cnt[ei[nE + e]], 1);
}

__global__ void scan1_kernel() {
    __shared__ int sm[1024];
    int t = threadIdx.x, b = blockIdx.x;
    int i = b * 1024 + t;
    sm[t] = (i < NN) ? g_cnt[i] : 0;
    __syncthreads();
    #pragma unroll
    for (int off = 1; off < 1024; off <<= 1) {
        int add = (t >= off) ? sm[t - off] : 0;
        __syncthreads();
        sm[t] += add;
        __syncthreads();
    }
    if (i < NN) g_inc[i] = sm[t];
    if (t == 1023) g_bsums[b] = sm[t];
}

__global__ void scan2_kernel(int nb) {
    __shared__ int sm[128];
    int t = threadIdx.x;
    int v = (t < nb) ? g_bsums[t] : 0;
    sm[t] = v;
    __syncthreads();
    #pragma unroll
    for (int off = 1; off < 128; off <<= 1) {
        int add = (t >= off) ? sm[t - off] : 0;
        __syncthreads();
        sm[t] += add;
        __syncthreads();
    }
    if (t < nb) g_bsums[t] = sm[t] - v;
}

__global__ void scan3_kernel() {
    int i = blockIdx.x * blockDim.x + threadIdx.x;
    if (i < NN) {
        int rs = g_inc[i] - g_cnt[i] + g_bsums[i >> 10];
        g_rs[i] = rs;
        g_cur[i] = rs;
    }
}

__global__ void fill_kernel(const int* __restrict__ ei, int nE) {
    int e = blockIdx.x * blockDim.x + threadIdx.x;
    if (e < nE) {
        int s = ei[e], d = ei[nE + e];
        int pos = atomicAdd(&g_cur[d], 1);
        g_srcs[pos] = s;
    }
}

// ---------------------------------------------------------------------------
// Prep W: fp32 [k][n] -> bf16 hi/lo swizzled images. grid=3.
// ---------------------------------------------------------------------------
__global__ void prep_w_kernel(const float* __restrict__ W1,
                              const float* __restrict__ W2,
                              const float* __restrict__ W3) {
    const float* W = (blockIdx.x == 0) ? W1 : (blockIdx.x == 1) ? W2 : W3;
    char* hi = (char*)g_w_hi + (size_t)blockIdx.x * 32768;
    char* lo = (char*)g_w_lo + (size_t)blockIdx.x * 32768;
    for (int i = threadIdx.x; i < D * D / 4; i += blockDim.x) {
        int k = i >> 5, c4 = i & 31;
        float4 v = ((const float4*)W)[i];
        float hx = __bfloat162float(__float2bfloat16(v.x));
        float hy = __bfloat162float(__float2bfloat16(v.y));
        float hz = __bfloat162float(__float2bfloat16(v.z));
        float hw = __bfloat162float(__float2bfloat16(v.w));
        uint2 hv = make_uint2(pack_bf2(v.x, v.y), pack_bf2(v.z, v.w));
        uint2 lv = make_uint2(pack_bf2(v.x - hx, v.y - hy), pack_bf2(v.z - hz, v.w - hw));
        uint32_t off = toff(k, c4 >> 1) + (c4 & 1) * 8;
        *(uint2*)(hi + off) = hv;
        *(uint2*)(lo + off) = lv;
    }
}

// ---------------------------------------------------------------------------
// Gather: warp per node (standalone, high occupancy, BW-bound).
// ---------------------------------------------------------------------------
__global__ __launch_bounds__(256)
void gather_kernel(const float* __restrict__ x, float* __restrict__ h) {
    int n = blockIdx.x * 8 + (threadIdx.x >> 5);
    if (n >= NN) return;
    int lane = threadIdx.x & 31;
    const float4* xv = (const float4*)x;

    float4 a0 = xv[(size_t)n * 32 + lane];
    float4 a1 = make_float4(0.f, 0.f, 0.f, 0.f);
    float4 a2 = a1, a3 = a1;

    int start = g_rs[n], c = g_cnt[n];
    const int* sp = g_srcs + start;
    int j = 0;
    for (; j + 4 <= c; j += 4) {
        int s0 = sp[j], s1 = sp[j + 1], s2 = sp[j + 2], s3 = sp[j + 3];
        a0 = add4(a0, xv[(size_t)s0 * 32 + lane]);
        a1 = add4(a1, xv[(size_t)s1 * 32 + lane]);
        a2 = add4(a2, xv[(size_t)s2 * 32 + lane]);
        a3 = add4(a3, xv[(size_t)s3 * 32 + lane]);
    }
    for (; j < c; j++)
        a0 = add4(a0, xv[(size_t)sp[j] * 32 + lane]);
    ((float4*)h)[(size_t)n * 32 + lane] = add4(add4(a0, a1), add4(a2, a3));
}

// ---------------------------------------------------------------------------
// Shared GEMM building blocks (split-bf16 HMMA, 128x128 tile, K=128).
// A-lo image is always at a_off + 32768; W-lo at w_off + 32768.
// ---------------------------------------------------------------------------
static __device__ __forceinline__ void mma_mainloop(
    uint32_t sb, uint32_t w_off, uint32_t a_off, int wid, int lane,
    float acc[16][4]) {
    #pragma unroll
    for (int i = 0; i < 16; i++)
        #pragma unroll
        for (int j = 0; j < 4; j++) acc[i][j] = 0.f;

    int mrow = wid * 16;
    int arow = mrow + (lane & 15);
    int asel = lane >> 4;
    int axor = arow & 7;
    uint32_t a_base = sb + a_off + (uint32_t)arow * 256u;
    int brow = lane & 15;
    int bsel = lane >> 4;

    #pragma unroll
    for (int ks = 0; ks < 8; ks++) {
        uint32_t ag = (uint32_t)(((ks * 2 + asel) ^ axor) << 4);
        uint32_t ahi[4], alo[4];
        ldsm_x4(ahi, a_base + ag);
        ldsm_x4(alo, a_base + 32768u + ag);

        int brr = ks * 16 + brow;
        uint32_t b_base = sb + w_off + (uint32_t)brr * 256u;
        int bxor = brr & 7;

        #pragma unroll
        for (int p = 0; p < 8; p++) {
            uint32_t bg = (uint32_t)(((p * 2 + bsel) ^ bxor) << 4);
            uint32_t bh[4], bl[4];
            ldsm_x4t(bh, b_base + bg);
            ldsm_x4t(bl, b_base + 32768u + bg);
            mma16816(acc[2 * p],     ahi, bh[0], bh[1]);
            mma16816(acc[2 * p + 1], ahi, bh[2], bh[3]);
            mma16816(acc[2 * p],     ahi, bl[0], bl[1]);
            mma16816(acc[2 * p + 1], ahi, bl[2], bl[3]);
            mma16816(acc[2 * p],     alo, bh[0], bh[1]);
            mma16816(acc[2 * p + 1], alo, bh[2], bh[3]);
        }
    }
}

// bias + relu -> fp32 gmem rows
static __device__ __forceinline__ void epilogue_gmem(
    float acc[16][4], const float* bs, int wid, int lane, int row0,
    float* __restrict__ hout) {
    int rbase = wid * 16 + (lane >> 2);
    int col0 = (lane & 3) * 2;
    #pragma unroll
    for (int half = 0; half < 2; half++) {
        int grow = row0 + rbase + half * 8;
        if (grow < NN) {
            float* op = hout + (size_t)grow * D;
            #pragma unroll
            for (int nt = 0; nt < 16; nt++) {
                int c = nt * 8 + col0;
                float2 o;
                o.x = fmaxf(acc[nt][half * 2 + 0] + bs[c], 0.f);
                o.y = fmaxf(acc[nt][half * 2 + 1] + bs[c + 1], 0.f);
                *(float2*)(op + c) = o;
            }
        }
    }
}

// bias + relu -> bf16 hi/lo smem tile images (next layer's A operand)
static __device__ __forceinline__ void epilogue_smem(
    float acc[16][4], const float* bs, int wid, int lane,
    char* smem, uint32_t a_off) {
    int rbase = wid * 16 + (lane >> 2);
    int col0 = (lane & 3) * 2;
    #pragma unroll
    for (int half = 0; half < 2; half++) {
        int row = rbase + half * 8;
        #pragma unroll
        for (int nt = 0; nt < 16; nt++) {
            int c = nt * 8 + col0;
            float v0 = fmaxf(acc[nt][half * 2 + 0] + bs[c], 0.f);
            float v1 = fmaxf(acc[nt][half * 2 + 1] + bs[c + 1], 0.f);
            float h0 = __bfloat162float(__float2bfloat16(v0));
            float h1 = __bfloat162float(__float2bfloat16(v1));
            uint32_t off = toff(row, nt) + (uint32_t)col0 * 2u;
            *(uint32_t*)(smem + a_off + off) = pack_bf2(v0, v1);
            *(uint32_t*)(smem + a_off + 32768u + off) = pack_bf2(v0 - h0, v1 - h1);
        }
    }
}

// stage fp32 rows -> bf16 hi/lo swizzled A images in smem
static __device__ __forceinline__ void stage_a(
    char* smem, uint32_t a_off, const float* __restrict__ hin,
    int row0, int tid) {
    #pragma unroll
    for (int t = 0; t < 16; t++) {
        int i = tid + t * 256;
        int row = i >> 5, c4 = i & 31;
        int grow = row0 + row;
        float4 v = make_float4(0.f, 0.f, 0.f, 0.f);
        if (grow < NN) v = ((const float4*)(hin + (size_t)grow * D))[c4];
        float hx = __bfloat162float(__float2bfloat16(v.x));
        float hy = __bfloat162float(__float2bfloat16(v.y));
        float hz = __bfloat162float(__float2bfloat16(v.z));
        float hw = __bfloat162float(__float2bfloat16(v.w));
        uint2 hv = make_uint2(pack_bf2(v.x, v.y), pack_bf2(v.z, v.w));
        uint2 lv = make_uint2(pack_bf2(v.x - hx, v.y - hy), pack_bf2(v.z - hz, v.w - hw));
        uint32_t off = toff(row, c4 >> 1) + (c4 & 1) * 8;
        *(uint2*)(smem + a_off + off) = hv;
        *(uint2*)(smem + a_off + 32768u + off) = lv;
    }
}

// ---------------------------------------------------------------------------
// Layer 1: one CTA per 128-row tile. Smem: WH WL AH AL bias = 128.5KB.
// ---------------------------------------------------------------------------
#define L1_W  0u
#define L1_A  65536u
#define L1_B  131072u
#define L1_SM (131072 + 512)

__global__ __launch_bounds__(256, 1)
void layer1_kernel(const float* __restrict__ hin,
                   const uint4* __restrict__ Whi, const uint4* __restrict__ Wlo,
                   const float* __restrict__ bias,
                   float* __restrict__ hout) {
    extern __shared__ char smem[];
    uint32_t sb = s2u(smem);
    int tid = threadIdx.x, wid = tid >> 5, lane = tid & 31;
    int row0 = blockIdx.x * 128;

    #pragma unroll
    for (int t = 0; t < 8; t++) {
        int i = tid + t * 256;
        ((uint4*)(smem + L1_W))[i]          = Whi[i];
        ((uint4*)(smem + L1_W + 32768))[i]  = Wlo[i];
    }
    stage_a(smem, L1_A, hin, row0, tid);
    if (tid < 32) ((float4*)(smem + L1_B))[tid] = ((const float4*)bias)[tid];
    __syncthreads();

    float acc[16][4];
    mma_mainloop(sb, L1_W, L1_A, wid, lane, acc);
    epilogue_gmem(acc, (const float*)(smem + L1_B), wid, lane, row0, hout);
}

// ---------------------------------------------------------------------------
// Layers 2+3 fused: one CTA per tile. Smem: W2(64K) W3(64K) A(64K) b2 b3
//   = 193KB. MMA(W2) -> bias/relu -> re-emit A in smem -> MMA(W3) -> out.
// ---------------------------------------------------------------------------
#define F_W2  0u
#define F_W3  65536u
#define F_A   131072u
#define F_B2  196608u
#define F_B3  197120u
#define F_SM  (196608 + 1024)

__global__ __launch_bounds__(256, 1)
void layer23_kernel(const float* __restrict__ hin,
                    const uint4* __restrict__ W2hi, const uint4* __restrict__ W2lo,
                    const uint4* __restrict__ W3hi, const uint4* __restrict__ W3lo,
                    const float* __restrict__ b2, const float* __restrict__ b3,
                    float* __restrict__ out) {
    extern __shared__ char smem[];
    uint32_t sb = s2u(smem);
    int tid = threadIdx.x, wid = tid >> 5, lane = tid & 31;
    int row0 = blockIdx.x * 128;

    {
        const uint4* srcs[4] = {W2hi, W2lo, W3hi, W3lo};
        #pragma unroll
        for (int t = 0; t < 32; t++) {
            int i = tid + t * 256;
            int m = i >> 11, idx = i & 2047;
            ((uint4*)(smem + m * 32768))[idx] = srcs[m][idx];
        }
    }
    stage_a(smem, F_A, hin, row0, tid);
    if (tid < 32)       ((float4*)(smem + F_B2))[tid]      = ((const float4*)b2)[tid];
    else if (tid < 64)  ((float4*)(smem + F_B3))[tid - 32] = ((const float4*)b3)[tid - 32];
    __syncthreads();

    float acc[16][4];
    mma_mainloop(sb, F_W2, F_A, wid, lane, acc);
    __syncthreads();   // all warps done READING A before overwrite
    epilogue_smem(acc, (const float*)(smem + F_B2), wid, lane, smem, F_A);
    __syncthreads();
    mma_mainloop(sb, F_W3, F_A, wid, lane, acc);
    epilogue_gmem(acc, (const float*)(smem + F_B3), wid, lane, row0, out);
}

// ---------------------------------------------------------------------------
extern "C" void kernel_launch(void* const* d_in, const int* in_sizes, int n_in,
                              void* d_out, int out_size) {
    const float* x  = (const float*)d_in[0];
    const float* W1 = (const float*)d_in[1];
    const float* b1 = (const float*)d_in[2];
    const float* W2 = (const float*)d_in[3];
    const float* b2 = (const float*)d_in[4];
    const float* W3 = (const float*)d_in[5];
    const float* b3 = (const float*)d_in[6];
    const int*   ei = (const int*)d_in[7];   // int32 (JAX x64 disabled)
    float* out = (float*)d_out;

    int nE = in_sizes[7] / 2;
    if (nE > MAXE) nE = MAXE;

    float *h0, *h1;
    uint4 *wHi, *wLo;
    cudaGetSymbolAddress((void**)&h0, g_h0);
    cudaGetSymbolAddress((void**)&h1, g_h1);
    cudaGetSymbolAddress((void**)&wHi, g_w_hi);
    cudaGetSymbolAddress((void**)&wLo, g_w_lo);

    // --- CSR build + weight prep ---
    zero_cnt_kernel<<<(NN + 255) / 256, 256>>>();
    prep_w_kernel<<<3, 256>>>(W1, W2, W3);
    hist_kernel<<<(nE + 255) / 256, 256>>>(ei, nE);
    int nb = (NN + 1023) / 1024;
    scan1_kernel<<<nb, 1024>>>();
    scan2_kernel<<<1, 128>>>(nb);
    scan3_kernel<<<(NN + 255) / 256, 256>>>();
    fill_kernel<<<(nE + 255) / 256, 256>>>(ei, nE);

    // --- gather ---
    gather_kernel<<<(NN + 7) / 8, 256>>>(x, h0);

    // --- layer 1, then fused layers 2+3 ---
    cudaFuncSetAttribute(layer1_kernel,
                         cudaFuncAttributeMaxDynamicSharedMemorySize, L1_SM);
    cudaFuncSetAttribute(layer23_kernel,
                         cudaFuncAttributeMaxDynamicSharedMemorySize, F_SM);
    layer1_kernel<<<NT, 256, L1_SM>>>(h0, wHi, wLo, b1, h1);
    layer23_kernel<<<NT, 256, F_SM>>>(h1,
                                      wHi + TILE_U4,     wLo + TILE_U4,
                                      wHi + 2 * TILE_U4, wLo + 2 * TILE_U4,
                                      b2, b3, out);
}

// round 8
// speedup vs baseline: 1.4265x; 1.0375x over previous
#include <cuda_runtime.h>
#include <cuda_bf16.h>
#include <cstdint>

#define NN   100000
#define D    128
#define MAXE 3400000
#define NT   ((NN + 127) / 128)
#define TILE_U4 2048   // uint4 per 32KB bf16 128x128 image

// ---------------------------------------------------------------------------
// Allocation-free scratch
// ---------------------------------------------------------------------------
__device__ float g_h0[(size_t)NN * D];
__device__ int   g_cnt[NN];
__device__ int   g_inc[NN];
__device__ int   g_rs[NN];
__device__ int   g_cur[NN];
__device__ int   g_srcs[MAXE];
__device__ int   g_bsums[128];
__device__ uint4 g_w_hi[3 * TILE_U4];
__device__ uint4 g_w_lo[3 * TILE_U4];

static __device__ __forceinline__ float4 add4(float4 a, float4 b) {
    return make_float4(a.x + b.x, a.y + b.y, a.z + b.z, a.w + b.w);
}

static __device__ __forceinline__ uint32_t s2u(const void* p) {
    uint32_t a;
    asm("{ .reg .u64 t; cvta.to.shared.u64 t, %1; cvt.u32.u64 %0, t; }"
        : "=r"(a) : "l"(p));
    return a;
}

static __device__ __forceinline__ uint32_t pack_bf2(float a, float b) {
    __nv_bfloat162 t = __floats2bfloat162_rn(a, b);
    return *(uint32_t*)&t;
}

static __device__ __forceinline__ void mma16816(float* c, const uint32_t* a,
                                                uint32_t b0, uint32_t b1) {
    asm volatile(
        "mma.sync.aligned.m16n8k16.row.col.f32.bf16.bf16.f32 "
        "{%0,%1,%2,%3}, {%4,%5,%6,%7}, {%8,%9}, {%0,%1,%2,%3};"
        : "+f"(c[0]), "+f"(c[1]), "+f"(c[2]), "+f"(c[3])
        : "r"(a[0]), "r"(a[1]), "r"(a[2]), "r"(a[3]), "r"(b0), "r"(b1));
}

static __device__ __forceinline__ void ldsm_x4(uint32_t* r, uint32_t addr) {
    asm volatile("ldmatrix.sync.aligned.m8n8.x4.shared.b16 {%0,%1,%2,%3}, [%4];"
                 : "=r"(r[0]), "=r"(r[1]), "=r"(r[2]), "=r"(r[3]) : "r"(addr));
}
static __device__ __forceinline__ void ldsm_x4t(uint32_t* r, uint32_t addr) {
    asm volatile("ldmatrix.sync.aligned.m8n8.x4.trans.shared.b16 {%0,%1,%2,%3}, [%4];"
                 : "=r"(r[0]), "=r"(r[1]), "=r"(r[2]), "=r"(r[3]) : "r"(addr));
}

static __device__ __forceinline__ void cpa16(uint32_t dst, const void* src) {
    asm volatile("cp.async.cg.shared.global [%0], [%1], 16;"
                 :: "r"(dst), "l"(src) : "memory");
}

// tile byte offset: row-major 128x128 bf16, 256B/row, XOR-swizzled 16B groups
static __device__ __forceinline__ uint32_t toff(int row, int g) {
    return (uint32_t)row * 256u + (uint32_t)((g ^ (row & 7)) << 4);
}

// ---------------------------------------------------------------------------
// CSR build
// ---------------------------------------------------------------------------
__global__ void hist_kernel(const int* __restrict__ ei, int nE) {
    int e = blockIdx.x * blockDim.x + threadIdx.x;
    if (e < nE) atomicAdd(&g_cnt[ei[nE + e]], 1);
}

__global__ void scan1_kernel() {
    __shared__ int sm[1024];
    int t = threadIdx.x, b = blockIdx.x;
    int i = b * 1024 + t;
    sm[t] = (i < NN) ? g_cnt[i] : 0;
    __syncthreads();
    #pragma unroll
    for (int off = 1; off < 1024; off <<= 1) {
        int add = (t >= off) ? sm[t - off] : 0;
        __syncthreads();
        sm[t] += add;
        __syncthreads();
    }
    if (i < NN) g_inc[i] = sm[t];
    if (t == 1023) g_bsums[b] = sm[t];
}

__global__ void scan2_kernel(int nb) {
    __shared__ int sm[128];
    int t = threadIdx.x;
    int v = (t < nb) ? g_bsums[t] : 0;
    sm[t] = v;
    __syncthreads();
    #pragma unroll
    for (int off = 1; off < 128; off <<= 1) {
        int add = (t >= off) ? sm[t - off] : 0;
        __syncthreads();
        sm[t] += add;
        __syncthreads();
    }
    if (t < nb) g_bsums[t] = sm[t] - v;
}

__global__ void scan3_kernel() {
    int i = blockIdx.x * blockDim.x + threadIdx.x;
    if (i < NN) {
        int rs = g_inc[i] - g_cnt[i] + g_bsums[i >> 10];
        g_rs[i] = rs;
        g_cur[i] = rs;
    }
}

__global__ void fill_kernel(const int* __restrict__ ei, int nE) {
    int e = blockIdx.x * blockDim.x + threadIdx.x;
    if (e < nE) {
        int s = ei[e], d = ei[nE + e];
        int pos = atomicAdd(&g_cur[d], 1);
        g_srcs[pos] = s;
    }
}

// ---------------------------------------------------------------------------
// Prep W: fp32 [k][n] -> bf16 hi/lo swizzled images. grid=3.
// ---------------------------------------------------------------------------
__global__ void prep_w_kernel(const float* __restrict__ W1,
                              const float* __restrict__ W2,
                              const float* __restrict__ W3) {
    const float* W = (blockIdx.x == 0) ? W1 : (blockIdx.x == 1) ? W2 : W3;
    char* hi = (char*)g_w_hi + (size_t)blockIdx.x * 32768;
    char* lo = (char*)g_w_lo + (size_t)blockIdx.x * 32768;
    for (int i = threadIdx.x; i < D * D / 4; i += blockDim.x) {
        int k = i >> 5, c4 = i & 31;
        float4 v = ((const float4*)W)[i];
        float hx = __bfloat162float(__float2bfloat16(v.x));
        float hy = __bfloat162float(__float2bfloat16(v.y));
        float hz = __bfloat162float(__float2bfloat16(v.z));
        float hw = __bfloat162float(__float2bfloat16(v.w));
        uint2 hv = make_uint2(pack_bf2(v.x, v.y), pack_bf2(v.z, v.w));
        uint2 lv = make_uint2(pack_bf2(v.x - hx, v.y - hy), pack_bf2(v.z - hz, v.w - hw));
        uint32_t off = toff(k, c4 >> 1) + (c4 & 1) * 8;
        *(uint2*)(hi + off) = hv;
        *(uint2*)(lo + off) = lv;
    }
}

// ---------------------------------------------------------------------------
// Gather: warp per node (standalone, high occupancy, L2-BW-bound).
// ---------------------------------------------------------------------------
__global__ __launch_bounds__(256)
void gather_kernel(const float* __restrict__ x, float* __restrict__ h) {
    int n = blockIdx.x * 8 + (threadIdx.x >> 5);
    if (n >= NN) return;
    int lane = threadIdx.x & 31;
    const float4* xv = (const float4*)x;

    float4 a0 = xv[(size_t)n * 32 + lane];
    float4 a1 = make_float4(0.f, 0.f, 0.f, 0.f);
    float4 a2 = a1, a3 = a1;

    int start = g_rs[n], c = g_cnt[n];
    const int* sp = g_srcs + start;
    int j = 0;
    for (; j + 4 <= c; j += 4) {
        int s0 = sp[j], s1 = sp[j + 1], s2 = sp[j + 2], s3 = sp[j + 3];
        a0 = add4(a0, xv[(size_t)s0 * 32 + lane]);
        a1 = add4(a1, xv[(size_t)s1 * 32 + lane]);
        a2 = add4(a2, xv[(size_t)s2 * 32 + lane]);
        a3 = add4(a3, xv[(size_t)s3 * 32 + lane]);
    }
    for (; j < c; j++)
        a0 = add4(a0, xv[(size_t)sp[j] * 32 + lane]);
    ((float4*)h)[(size_t)n * 32 + lane] = add4(add4(a0, a1), add4(a2, a3));
}

// ---------------------------------------------------------------------------
// Shared GEMM building blocks (split-bf16 HMMA, 128x128 tile, K=128).
// lo image always at +32768 within its region.
// ---------------------------------------------------------------------------
static __device__ __forceinline__ void mma_mainloop(
    uint32_t sb, uint32_t w_off, uint32_t a_off, int wid, int lane,
    float acc[16][4]) {
    #pragma unroll
    for (int i = 0; i < 16; i++)
        #pragma unroll
        for (int j = 0; j < 4; j++) acc[i][j] = 0.f;

    int mrow = wid * 16;
    int arow = mrow + (lane & 15);
    int asel = lane >> 4;
    int axor = arow & 7;
    uint32_t a_base = sb + a_off + (uint32_t)arow * 256u;
    int brow = lane & 15;
    int bsel = lane >> 4;

    #pragma unroll
    for (int ks = 0; ks < 8; ks++) {
        uint32_t ag = (uint32_t)(((ks * 2 + asel) ^ axor) << 4);
        uint32_t ahi[4], alo[4];
        ldsm_x4(ahi, a_base + ag);
        ldsm_x4(alo, a_base + 32768u + ag);

        int brr = ks * 16 + brow;
        uint32_t b_base = sb + w_off + (uint32_t)brr * 256u;
        int bxor = brr & 7;

        #pragma unroll
        for (int p = 0; p < 8; p++) {
            uint32_t bg = (uint32_t)(((p * 2 + bsel) ^ bxor) << 4);
            uint32_t bh[4], bl[4];
            ldsm_x4t(bh, b_base + bg);
            ldsm_x4t(bl, b_base + 32768u + bg);
            mma16816(acc[2 * p],     ahi, bh[0], bh[1]);
            mma16816(acc[2 * p + 1], ahi, bh[2], bh[3]);
            mma16816(acc[2 * p],     ahi, bl[0], bl[1]);
            mma16816(acc[2 * p + 1], ahi, bl[2], bl[3]);
            mma16816(acc[2 * p],     alo, bh[0], bh[1]);
            mma16816(acc[2 * p + 1], alo, bh[2], bh[3]);
        }
    }
}

// bias + relu -> fp32 gmem rows
static __device__ __forceinline__ void epilogue_gmem(
    float acc[16][4], const float* bs, int wid, int lane, int row0,
    float* __restrict__ hout) {
    int rbase = wid * 16 + (lane >> 2);
    int col0 = (lane & 3) * 2;
    #pragma unroll
    for (int half = 0; half < 2; half++) {
        int grow = row0 + rbase + half * 8;
        if (grow < NN) {
            float* op = hout + (size_t)grow * D;
            #pragma unroll
            for (int nt = 0; nt < 16; nt++) {
                int c = nt * 8 + col0;
                float2 o;
                o.x = fmaxf(acc[nt][half * 2 + 0] + bs[c], 0.f);
                o.y = fmaxf(acc[nt][half * 2 + 1] + bs[c + 1], 0.f);
                *(float2*)(op + c) = o;
            }
        }
    }
}

// bias + relu -> bf16 hi/lo smem tile images (next GEMM's A operand)
static __device__ __forceinline__ void epilogue_smem(
    float acc[16][4], const float* bs, int wid, int lane,
    char* smem, uint32_t a_off) {
    int rbase = wid * 16 + (lane >> 2);
    int col0 = (lane & 3) * 2;
    #pragma unroll
    for (int half = 0; half < 2; half++) {
        int row = rbase + half * 8;
        #pragma unroll
        for (int nt = 0; nt < 16; nt++) {
            int c = nt * 8 + col0;
            float v0 = fmaxf(acc[nt][half * 2 + 0] + bs[c], 0.f);
            float v1 = fmaxf(acc[nt][half * 2 + 1] + bs[c + 1], 0.f);
            float h0 = __bfloat162float(__float2bfloat16(v0));
            float h1 = __bfloat162float(__float2bfloat16(v1));
            uint32_t off = toff(row, nt) + (uint32_t)col0 * 2u;
            *(uint32_t*)(smem + a_off + off) = pack_bf2(v0, v1);
            *(uint32_t*)(smem + a_off + 32768u + off) = pack_bf2(v0 - h0, v1 - h1);
        }
    }
}

// stage fp32 rows -> bf16 hi/lo swizzled A images in smem
static __device__ __forceinline__ void stage_a(
    char* smem, uint32_t a_off, const float* __restrict__ hin,
    int row0, int tid) {
    #pragma unroll
    for (int t = 0; t < 16; t++) {
        int i = tid + t * 256;
        int row = i >> 5, c4 = i & 31;
        int grow = row0 + row;
        float4 v = make_float4(0.f, 0.f, 0.f, 0.f);
        if (grow < NN) v = ((const float4*)(hin + (size_t)grow * D))[c4];
        float hx = __bfloat162float(__float2bfloat16(v.x));
        float hy = __bfloat162float(__float2bfloat16(v.y));
        float hz = __bfloat162float(__float2bfloat16(v.z));
        float hw = __bfloat162float(__float2bfloat16(v.w));
        uint2 hv = make_uint2(pack_bf2(v.x, v.y), pack_bf2(v.z, v.w));
        uint2 lv = make_uint2(pack_bf2(v.x - hx, v.y - hy), pack_bf2(v.z - hz, v.w - hw));
        uint32_t off = toff(row, c4 >> 1) + (c4 & 1) * 8;
        *(uint2*)(smem + a_off + off) = hv;
        *(uint2*)(smem + a_off + 32768u + off) = lv;
    }
}

// ---------------------------------------------------------------------------
// All 3 layers in one kernel, one CTA per 128-row tile.
// Regions (64KB each): R1@0, R2@65536, R3@131072. Biases after.
//   stage: W1->R1, W2->R2, A->R3
//   GEMM1(A@R3, W1@R1)           [R1,R3 dead after]
//   cp.async W3 -> R3 (hidden under GEMM2); epi1: A' -> R1
//   GEMM2(A'@R1, W2@R2)          [R2 dead after]
//   epi2: A'' -> R1 (overwrite)
//   GEMM3(A''@R1, W3@R3) -> out
// ---------------------------------------------------------------------------
#define R1_OFF 0u
#define R2_OFF 65536u
#define R3_OFF 131072u
#define B1_OFF 196608u
#define B2_OFF 197120u
#define B3_OFF 197632u
#define M3_SM  (196608 + 1536)

__global__ __launch_bounds__(256, 1)
void mlp3_kernel(const float* __restrict__ hin,
                 const uint4* __restrict__ W1hi, const uint4* __restrict__ W1lo,
                 const uint4* __restrict__ W2hi, const uint4* __restrict__ W2lo,
                 const uint4* __restrict__ W3hi, const uint4* __restrict__ W3lo,
                 const float* __restrict__ b1, const float* __restrict__ b2,
                 const float* __restrict__ b3,
                 float* __restrict__ out) {
    extern __shared__ char smem[];
    uint32_t sb = s2u(smem);
    int tid = threadIdx.x, wid = tid >> 5, lane = tid & 31;
    int row0 = blockIdx.x * 128;

    // stage W1, W2 (verbatim), A (convert), biases
    #pragma unroll
    for (int t = 0; t < 8; t++) {
        int i = tid + t * 256;
        ((uint4*)(smem + R1_OFF))[i]          = W1hi[i];
        ((uint4*)(smem + R1_OFF + 32768))[i]  = W1lo[i];
        ((uint4*)(smem + R2_OFF))[i]          = W2hi[i];
        ((uint4*)(smem + R2_OFF + 32768))[i]  = W2lo[i];
    }
    stage_a(smem, R3_OFF, hin, row0, tid);
    if (tid < 32)       ((float4*)(smem + B1_OFF))[tid]      = ((const float4*)b1)[tid];
    else if (tid < 64)  ((float4*)(smem + B2_OFF))[tid - 32] = ((const float4*)b2)[tid - 32];
    else if (tid < 96)  ((float4*)(smem + B3_OFF))[tid - 64] = ((const float4*)b3)[tid - 64];
    __syncthreads();

    float acc[16][4];
    // GEMM1
    mma_mainloop(sb, R1_OFF, R3_OFF, wid, lane, acc);
    __syncthreads();   // everyone done reading R1(W1) and R3(A)

    // W3 -> R3, hidden under GEMM2
    #pragma unroll
    for (int t = 0; t < 8; t++) {
        int i = tid + t * 256;
        cpa16(sb + R3_OFF + (uint32_t)i * 16u, W3hi + i);
        cpa16(sb + R3_OFF + 32768u + (uint32_t)i * 16u, W3lo + i);
    }
    asm volatile("cp.async.commit_group;" ::: "memory");

    epilogue_smem(acc, (const float*)(smem + B1_OFF), wid, lane, smem, R1_OFF);
    __syncthreads();   // A' visible

    // GEMM2
    mma_mainloop(sb, R2_OFF, R1_OFF, wid, lane, acc);
    asm volatile("cp.async.wait_group 0;" ::: "memory");
    __syncthreads();   // everyone done reading R1(A'); W3 landed in R3

    epilogue_smem(acc, (const float*)(smem + B2_OFF), wid, lane, smem, R1_OFF);
    __syncthreads();   // A'' visible

    // GEMM3
    mma_mainloop(sb, R3_OFF, R1_OFF, wid, lane, acc);
    epilogue_gmem(acc, (const float*)(smem + B3_OFF), wid, lane, row0, out);
}

// ---------------------------------------------------------------------------
extern "C" void kernel_launch(void* const* d_in, const int* in_sizes, int n_in,
                              void* d_out, int out_size) {
    const float* x  = (const float*)d_in[0];
    const float* W1 = (const float*)d_in[1];
    const float* b1 = (const float*)d_in[2];
    const float* W2 = (const float*)d_in[3];
    const float* b2 = (const float*)d_in[4];
    const float* W3 = (const float*)d_in[5];
    const float* b3 = (const float*)d_in[6];
    const int*   ei = (const int*)d_in[7];   // int32 (JAX x64 disabled)
    float* out = (float*)d_out;

    int nE = in_sizes[7] / 2;
    if (nE > MAXE) nE = MAXE;

    float* h0;
    int* cnt;
    uint4 *wHi, *wLo;
    cudaGetSymbolAddress((void**)&h0, g_h0);
    cudaGetSymbolAddress((void**)&cnt, g_cnt);
    cudaGetSymbolAddress((void**)&wHi, g_w_hi);
    cudaGetSymbolAddress((void**)&wLo, g_w_lo);

    // --- CSR build + weight prep ---
    cudaMemsetAsync(cnt, 0, NN * sizeof(int));
    prep_w_kernel<<<3, 256>>>(W1, W2, W3);
    hist_kernel<<<(nE + 255) / 256, 256>>>(ei, nE);
    int nb = (NN + 1023) / 1024;
    scan1_kernel<<<nb, 1024>>>();
    scan2_kernel<<<1, 128>>>(nb);
    scan3_kernel<<<(NN + 255) / 256, 256>>>();
    fill_kernel<<<(nE + 255) / 256, 256>>>(ei, nE);

    // --- gather: h0 = x + segment_sum(x[src] -> dst) ---
    gather_kernel<<<(NN + 7) / 8, 256>>>(x, h0);

    // --- fused 3-layer MLP ---
    cudaFuncSetAttribute(mlp3_kernel,
                         cudaFuncAttributeMaxDynamicSharedMemorySize, M3_SM);
    mlp3_kernel<<<NT, 256, M3_SM>>>(h0,
                                    wHi,               wLo,
                                    wHi + TILE_U4,     wLo + TILE_U4,
                                    wHi + 2 * TILE_U4, wLo + 2 * TILE_U4,
                                    b1, b2, b3, out);
}

// round 9
// speedup vs baseline: 1.6524x; 1.1583x over previous
#include <cuda_runtime.h>
#include <cuda_bf16.h>
#include <cuda_fp16.h>
#include <cstdint>

#define NN   100000
#define D    128
#define MAXE 3400000
#define NT   ((NN + 127) / 128)
#define TILE_U4 2048   // uint4 per 32KB bf16 128x128 image

// ---------------------------------------------------------------------------
// Allocation-free scratch
// ---------------------------------------------------------------------------
__device__ float  g_h0[(size_t)NN * D];
__device__ __half g_xh[(size_t)NN * D];   // fp16 copy of x (gather operand)
__device__ int    g_cnt[NN];
__device__ int    g_inc[NN];
__device__ int    g_rs[NN];
__device__ int    g_cur[NN];
__device__ int    g_srcs[MAXE];
__device__ int    g_bsums[128];
__device__ uint4  g_w_hi[3 * TILE_U4];
__device__ uint4  g_w_lo[3 * TILE_U4];

static __device__ __forceinline__ uint32_t s2u(const void* p) {
    uint32_t a;
    asm("{ .reg .u64 t; cvta.to.shared.u64 t, %1; cvt.u32.u64 %0, t; }"
        : "=r"(a) : "l"(p));
    return a;
}

static __device__ __forceinline__ uint32_t pack_bf2(float a, float b) {
    __nv_bfloat162 t = __floats2bfloat162_rn(a, b);
    return *(uint32_t*)&t;
}

static __device__ __forceinline__ void mma16816(float* c, const uint32_t* a,
                                                uint32_t b0, uint32_t b1) {
    asm volatile(
        "mma.sync.aligned.m16n8k16.row.col.f32.bf16.bf16.f32 "
        "{%0,%1,%2,%3}, {%4,%5,%6,%7}, {%8,%9}, {%0,%1,%2,%3};"
        : "+f"(c[0]), "+f"(c[1]), "+f"(c[2]), "+f"(c[3])
        : "r"(a[0]), "r"(a[1]), "r"(a[2]), "r"(a[3]), "r"(b0), "r"(b1));
}

static __device__ __forceinline__ void ldsm_x4(uint32_t* r, uint32_t addr) {
    asm volatile("ldmatrix.sync.aligned.m8n8.x4.shared.b16 {%0,%1,%2,%3}, [%4];"
                 : "=r"(r[0]), "=r"(r[1]), "=r"(r[2]), "=r"(r[3]) : "r"(addr));
}
static __device__ __forceinline__ void ldsm_x4t(uint32_t* r, uint32_t addr) {
    asm volatile("ldmatrix.sync.aligned.m8n8.x4.trans.shared.b16 {%0,%1,%2,%3}, [%4];"
                 : "=r"(r[0]), "=r"(r[1]), "=r"(r[2]), "=r"(r[3]) : "r"(addr));
}

static __device__ __forceinline__ void cpa16(uint32_t dst, const void* src) {
    asm volatile("cp.async.cg.shared.global [%0], [%1], 16;"
                 :: "r"(dst), "l"(src) : "memory");
}

// tile byte offset: row-major 128x128 bf16, 256B/row, XOR-swizzled 16B groups
static __device__ __forceinline__ uint32_t toff(int row, int g) {
    return (uint32_t)row * 256u + (uint32_t)((g ^ (row & 7)) << 4);
}

// ---------------------------------------------------------------------------
// x -> fp16 copy
// ---------------------------------------------------------------------------
__global__ void prep_x_kernel(const float4* __restrict__ x4, uint2* __restrict__ xh) {
    int i = blockIdx.x * blockDim.x + threadIdx.x;
    if (i < NN * D / 4) {
        float4 v = x4[i];
        __half2 h0 = __floats2half2_rn(v.x, v.y);
        __half2 h1 = __floats2half2_rn(v.z, v.w);
        xh[i] = make_uint2(*(uint32_t*)&h0, *(uint32_t*)&h1);
    }
}

// ---------------------------------------------------------------------------
// CSR build
// ---------------------------------------------------------------------------
__global__ void hist_kernel(const int* __restrict__ ei, int nE) {
    int e = blockIdx.x * blockDim.x + threadIdx.x;
    if (e < nE) atomicAdd(&g_cnt[ei[nE + e]], 1);
}

__global__ void scan1_kernel() {
    __shared__ int sm[1024];
    int t = threadIdx.x, b = blockIdx.x;
    int i = b * 1024 + t;
    sm[t] = (i < NN) ? g_cnt[i] : 0;
    __syncthreads();
    #pragma unroll
    for (int off = 1; off < 1024; off <<= 1) {
        int add = (t >= off) ? sm[t - off] : 0;
        __syncthreads();
        sm[t] += add;
        __syncthreads();
    }
    if (i < NN) g_inc[i] = sm[t];
    if (t == 1023) g_bsums[b] = sm[t];
}

// merged scan2+scan3: each block needs ONE bsum prefix (chunk = blockIdx>>2)
__global__ void scan3_kernel() {
    __shared__ int base_sh;
    int t = threadIdx.x;
    int chunk = (int)(blockIdx.x >> 2);   // 256-thr blocks, 1024-elem chunks
    if (t < 32) {
        int s = 0;
        for (int j = t; j < chunk; j += 32) s += g_bsums[j];
        #pragma unroll
        for (int o = 16; o; o >>= 1) s += __shfl_down_sync(0xFFFFFFFFu, s, o);
        if (t == 0) base_sh = s;
    }
    __syncthreads();
    int i = blockIdx.x * blockDim.x + t;
    if (i < NN) {
        int rs = g_inc[i] - g_cnt[i] + base_sh;
        g_rs[i] = rs;
        g_cur[i] = rs;
    }
}

__global__ void fill_kernel(const int* __restrict__ ei, int nE) {
    int e = blockIdx.x * blockDim.x + threadIdx.x;
    if (e < nE) {
        int s = ei[e], d = ei[nE + e];
        int pos = atomicAdd(&g_cur[d], 1);
        g_srcs[pos] = s;
    }
}

// ---------------------------------------------------------------------------
// Prep W: fp32 [k][n] -> bf16 hi/lo swizzled images. grid=3.
// ---------------------------------------------------------------------------
__global__ void prep_w_kernel(const float* __restrict__ W1,
                              const float* __restrict__ W2,
                              const float* __restrict__ W3) {
    const float* W = (blockIdx.x == 0) ? W1 : (blockIdx.x == 1) ? W2 : W3;
    char* hi = (char*)g_w_hi + (size_t)blockIdx.x * 32768;
    char* lo = (char*)g_w_lo + (size_t)blockIdx.x * 32768;
    for (int i = threadIdx.x; i < D * D / 4; i += blockDim.x) {
        int k = i >> 5, c4 = i & 31;
        float4 v = ((const float4*)W)[i];
        float hx = __bfloat162float(__float2bfloat16(v.x));
        float hy = __bfloat162float(__float2bfloat16(v.y));
        float hz = __bfloat162float(__float2bfloat16(v.z));
        float hw = __bfloat162float(__float2bfloat16(v.w));
        uint2 hv = make_uint2(pack_bf2(v.x, v.y), pack_bf2(v.z, v.w));
        uint2 lv = make_uint2(pack_bf2(v.x - hx, v.y - hy), pack_bf2(v.z - hz, v.w - hw));
        uint32_t off = toff(k, c4 >> 1) + (c4 & 1) * 8;
        *(uint2*)(hi + off) = hv;
        *(uint2*)(lo + off) = lv;
    }
}

// ---------------------------------------------------------------------------
// Gather: warp per node. Neighbors from fp16 copy (half bytes), self fp32.
// Lane owns cols [lane*4, lane*4+4): one uint2 (4 halves) per neighbor row.
// ---------------------------------------------------------------------------
static __device__ __forceinline__ void acc_half4(float4& a, uint2 raw) {
    float2 f0 = __half22float2(*(__half2*)&raw.x);
    float2 f1 = __half22float2(*(__half2*)&raw.y);
    a.x += f0.x; a.y += f0.y; a.z += f1.x; a.w += f1.y;
}

__global__ __launch_bounds__(256)
void gather_kernel(const float* __restrict__ x, float* __restrict__ h) {
    int n = blockIdx.x * 8 + (threadIdx.x >> 5);
    if (n >= NN) return;
    int lane = threadIdx.x & 31;
    const uint2* xh = (const uint2*)g_xh;   // 32 uint2 per row

    float4 a0 = ((const float4*)x)[(size_t)n * 32 + lane];   // self, fp32
    float4 a1 = make_float4(0.f, 0.f, 0.f, 0.f);
    float4 a2 = a1, a3 = a1;

    int start = g_rs[n], c = g_cnt[n];
    const int* sp = g_srcs + start;
    int j = 0;
    for (; j + 4 <= c; j += 4) {
        int s0 = sp[j], s1 = sp[j + 1], s2 = sp[j + 2], s3 = sp[j + 3];
        uint2 v0 = xh[(size_t)s0 * 32 + lane];
        uint2 v1 = xh[(size_t)s1 * 32 + lane];
        uint2 v2 = xh[(size_t)s2 * 32 + lane];
        uint2 v3 = xh[(size_t)s3 * 32 + lane];
        acc_half4(a0, v0); acc_half4(a1, v1);
        acc_half4(a2, v2); acc_half4(a3, v3);
    }
    for (; j < c; j++)
        acc_half4(a0, xh[(size_t)sp[j] * 32 + lane]);

    float4 s;
    s.x = (a0.x + a1.x) + (a2.x + a3.x);
    s.y = (a0.y + a1.y) + (a2.y + a3.y);
    s.z = (a0.z + a1.z) + (a2.z + a3.z);
    s.w = (a0.w + a1.w) + (a2.w + a3.w);
    ((float4*)h)[(size_t)n * 32 + lane] = s;
}

// ---------------------------------------------------------------------------
// Shared GEMM building blocks (split-bf16 HMMA, 128x128 tile, K=128).
// lo image always at +32768 within its region.
// ---------------------------------------------------------------------------
static __device__ __forceinline__ void mma_mainloop(
    uint32_t sb, uint32_t w_off, uint32_t a_off, int wid, int lane,
    float acc[16][4]) {
    #pragma unroll
    for (int i = 0; i < 16; i++)
        #pragma unroll
        for (int j = 0; j < 4; j++) acc[i][j] = 0.f;

    int mrow = wid * 16;
    int arow = mrow + (lane & 15);
    int asel = lane >> 4;
    int axor = arow & 7;
    uint32_t a_base = sb + a_off + (uint32_t)arow * 256u;
    int brow = lane & 15;
    int bsel = lane >> 4;

    #pragma unroll
    for (int ks = 0; ks < 8; ks++) {
        uint32_t ag = (uint32_t)(((ks * 2 + asel) ^ axor) << 4);
        uint32_t ahi[4], alo[4];
        ldsm_x4(ahi, a_base + ag);
        ldsm_x4(alo, a_base + 32768u + ag);

        int brr = ks * 16 + brow;
        uint32_t b_base = sb + w_off + (uint32_t)brr * 256u;
        int bxor = brr & 7;

        #pragma unroll
        for (int p = 0; p < 8; p++) {
            uint32_t bg = (uint32_t)(((p * 2 + bsel) ^ bxor) << 4);
            uint32_t bh[4], bl[4];
            ldsm_x4t(bh, b_base + bg);
            ldsm_x4t(bl, b_base + 32768u + bg);
            mma16816(acc[2 * p],     ahi, bh[0], bh[1]);
            mma16816(acc[2 * p + 1], ahi, bh[2], bh[3]);
            mma16816(acc[2 * p],     ahi, bl[0], bl[1]);
            mma16816(acc[2 * p + 1], ahi, bl[2], bl[3]);
            mma16816(acc[2 * p],     alo, bh[0], bh[1]);
            mma16816(acc[2 * p + 1], alo, bh[2], bh[3]);
        }
    }
}

// bias + relu -> fp32 gmem rows
static __device__ __forceinline__ void epilogue_gmem(
    float acc[16][4], const float* bs, int wid, int lane, int row0,
    float* __restrict__ hout) {
    int rbase = wid * 16 + (lane >> 2);
    int col0 = (lane & 3) * 2;
    #pragma unroll
    for (int half = 0; half < 2; half++) {
        int grow = row0 + rbase + half * 8;
        if (grow < NN) {
            float* op = hout + (size_t)grow * D;
            #pragma unroll
            for (int nt = 0; nt < 16; nt++) {
                int c = nt * 8 + col0;
                float2 o;
                o.x = fmaxf(acc[nt][half * 2 + 0] + bs[c], 0.f);
                o.y = fmaxf(acc[nt][half * 2 + 1] + bs[c + 1], 0.f);
                *(float2*)(op + c) = o;
            }
        }
    }
}

// bias + relu -> bf16 hi/lo smem tile images (next GEMM's A operand)
static __device__ __forceinline__ void epilogue_smem(
    float acc[16][4], const float* bs, int wid, int lane,
    char* smem, uint32_t a_off) {
    int rbase = wid * 16 + (lane >> 2);
    int col0 = (lane & 3) * 2;
    #pragma unroll
    for (int half = 0; half < 2; half++) {
        int row = rbase + half * 8;
        #pragma unroll
        for (int nt = 0; nt < 16; nt++) {
            int c = nt * 8 + col0;
            float v0 = fmaxf(acc[nt][half * 2 + 0] + bs[c], 0.f);
            float v1 = fmaxf(acc[nt][half * 2 + 1] + bs[c + 1], 0.f);
            float h0 = __bfloat162float(__float2bfloat16(v0));
            float h1 = __bfloat162float(__float2bfloat16(v1));
            uint32_t off = toff(row, nt) + (uint32_t)col0 * 2u;
            *(uint32_t*)(smem + a_off + off) = pack_bf2(v0, v1);
            *(uint32_t*)(smem + a_off + 32768u + off) = pack_bf2(v0 - h0, v1 - h1);
        }
    }
}

// stage fp32 rows -> bf16 hi/lo swizzled A images in smem
static __device__ __forceinline__ void stage_a(
    char* smem, uint32_t a_off, const float* __restrict__ hin,
    int row0, int tid) {
    #pragma unroll
    for (int t = 0; t < 16; t++) {
        int i = tid + t * 256;
        int row = i >> 5, c4 = i & 31;
        int grow = row0 + row;
        float4 v = make_float4(0.f, 0.f, 0.f, 0.f);
        if (grow < NN) v = ((const float4*)(hin + (size_t)grow * D))[c4];
        float hx = __bfloat162float(__float2bfloat16(v.x));
        float hy = __bfloat162float(__float2bfloat16(v.y));
        float hz = __bfloat162float(__float2bfloat16(v.z));
        float hw = __bfloat162float(__float2bfloat16(v.w));
        uint2 hv = make_uint2(pack_bf2(v.x, v.y), pack_bf2(v.z, v.w));
        uint2 lv = make_uint2(pack_bf2(v.x - hx, v.y - hy), pack_bf2(v.z - hz, v.w - hw));
        uint32_t off = toff(row, c4 >> 1) + (c4 & 1) * 8;
        *(uint2*)(smem + a_off + off) = hv;
        *(uint2*)(smem + a_off + 32768u + off) = lv;
    }
}

// ---------------------------------------------------------------------------
// All 3 layers in one kernel, one CTA per 128-row tile (R8 layout).
// ---------------------------------------------------------------------------
#define R1_OFF 0u
#define R2_OFF 65536u
#define R3_OFF 131072u
#define B1_OFF 196608u
#define B2_OFF 197120u
#define B3_OFF 197632u
#define M3_SM  (196608 + 1536)

__global__ __launch_bounds__(256, 1)
void mlp3_kernel(const float* __restrict__ hin,
                 const uint4* __restrict__ W1hi, const uint4* __restrict__ W1lo,
                 const uint4* __restrict__ W2hi, const uint4* __restrict__ W2lo,
                 const uint4* __restrict__ W3hi, const uint4* __restrict__ W3lo,
                 const float* __restrict__ b1, const float* __restrict__ b2,
                 const float* __restrict__ b3,
                 float* __restrict__ out) {
    extern __shared__ char smem[];
    uint32_t sb = s2u(smem);
    int tid = threadIdx.x, wid = tid >> 5, lane = tid & 31;
    int row0 = blockIdx.x * 128;

    #pragma unroll
    for (int t = 0; t < 8; t++) {
        int i = tid + t * 256;
        ((uint4*)(smem + R1_OFF))[i]          = W1hi[i];
        ((uint4*)(smem + R1_OFF + 32768))[i]  = W1lo[i];
        ((uint4*)(smem + R2_OFF))[i]          = W2hi[i];
        ((uint4*)(smem + R2_OFF + 32768))[i]  = W2lo[i];
    }
    stage_a(smem, R3_OFF, hin, row0, tid);
    if (tid < 32)       ((float4*)(smem + B1_OFF))[tid]      = ((const float4*)b1)[tid];
    else if (tid < 64)  ((float4*)(smem + B2_OFF))[tid - 32] = ((const float4*)b2)[tid - 32];
    else if (tid < 96)  ((float4*)(smem + B3_OFF))[tid - 64] = ((const float4*)b3)[tid - 64];
    __syncthreads();

    float acc[16][4];
    // GEMM1
    mma_mainloop(sb, R1_OFF, R3_OFF, wid, lane, acc);
    __syncthreads();

    // W3 -> R3, hidden under GEMM2
    #pragma unroll
    for (int t = 0; t < 8; t++) {
        int i = tid + t * 256;
        cpa16(sb + R3_OFF + (uint32_t)i * 16u, W3hi + i);
        cpa16(sb + R3_OFF + 32768u + (uint32_t)i * 16u, W3lo + i);
    }
    asm volatile("cp.async.commit_group;" ::: "memory");

    epilogue_smem(acc, (const float*)(smem + B1_OFF), wid, lane, smem, R1_OFF);
    __syncthreads();

    // GEMM2
    mma_mainloop(sb, R2_OFF, R1_OFF, wid, lane, acc);
    asm volatile("cp.async.wait_group 0;" ::: "memory");
    __syncthreads();

    epilogue_smem(acc, (const float*)(smem + B2_OFF), wid, lane, smem, R1_OFF);
    __syncthreads();

    // GEMM3
    mma_mainloop(sb, R3_OFF, R1_OFF, wid, lane, acc);
    epilogue_gmem(acc, (const float*)(smem + B3_OFF), wid, lane, row0, out);
}

// ---------------------------------------------------------------------------
extern "C" void kernel_launch(void* const* d_in, const int* in_sizes, int n_in,
                              void* d_out, int out_size) {
    const float* x  = (const float*)d_in[0];
    const float* W1 = (const float*)d_in[1];
    const float* b1 = (const float*)d_in[2];
    const float* W2 = (const float*)d_in[3];
    const float* b2 = (const float*)d_in[4];
    const float* W3 = (const float*)d_in[5];
    const float* b3 = (const float*)d_in[6];
    const int*   ei = (const int*)d_in[7];   // int32 (JAX x64 disabled)
    float* out = (float*)d_out;

    int nE = in_sizes[7] / 2;
    if (nE > MAXE) nE = MAXE;

    float* h0;
    int* cnt;
    uint2* xh;
    uint4 *wHi, *wLo;
    cudaGetSymbolAddress((void**)&h0, g_h0);
    cudaGetSymbolAddress((void**)&cnt, g_cnt);
    cudaGetSymbolAddress((void**)&xh, g_xh);
    cudaGetSymbolAddress((void**)&wHi, g_w_hi);
    cudaGetSymbolAddress((void**)&wLo, g_w_lo);

    // --- prep + CSR build ---
    cudaMemsetAsync(cnt, 0, NN * sizeof(int));
    prep_x_kernel<<<(NN * D / 4 + 255) / 256, 256>>>((const float4*)x, xh);
    prep_w_kernel<<<3, 256>>>(W1, W2, W3);
    hist_kernel<<<(nE + 255) / 256, 256>>>(ei, nE);
    int nb = (NN + 1023) / 1024;
    scan1_kernel<<<nb, 1024>>>();
    scan3_kernel<<<(NN + 255) / 256, 256>>>();
    fill_kernel<<<(nE + 255) / 256, 256>>>(ei, nE);

    // --- gather: h0 = x + segment_sum(x[src] -> dst), fp16 neighbor reads ---
    gather_kernel<<<(NN + 7) / 8, 256>>>(x, h0);

    // --- fused 3-layer MLP ---
    cudaFuncSetAttribute(mlp3_kernel,
                         cudaFuncAttributeMaxDynamicSharedMemorySize, M3_SM);
    mlp3_kernel<<<NT, 256, M3_SM>>>(h0,
                                    wHi,               wLo,
                                    wHi + TILE_U4,     wLo + TILE_U4,
                                    wHi + 2 * TILE_U4, wLo + 2 * TILE_U4,
                                    b1, b2, b3, out);
}